// round 1
// baseline (speedup 1.0000x reference)
#include <cuda_runtime.h>
#include <cstdint>

// Shapes fixed by the problem: B=16384, S=512, F=4, E=8, heads=2, Dh=4, H=16
#define FULLMASK 0xFFFFFFFFu

// Batch-invariant folded weights, produced by precompute_kernel.
__device__ float g_wfold[64];   // [p=8][i=8]  p = h*4+f
__device__ float g_bfold[8];

// ---------------------------------------------------------------------------
// Pre-kernel: self-attention over Q (batch invariant) + fold cross-attn q/k.
// ---------------------------------------------------------------------------
__global__ void precompute_kernel(const float* __restrict__ Q,
                                  const float* __restrict__ sa_w_in,
                                  const float* __restrict__ sa_b_in,
                                  const float* __restrict__ sa_w_out,
                                  const float* __restrict__ sa_b_out,
                                  const float* __restrict__ ca_w_in,
                                  const float* __restrict__ ca_b_in)
{
    if (threadIdx.x != 0) return;

    // qkv projections of Q [4,8]; packed weight rows: q=0..7, k=8..15, v=16..23
    float qh[4][8], kh[4][8], vh[4][8];
    for (int f = 0; f < 4; f++)
        for (int j = 0; j < 8; j++) {
            float aq = sa_b_in[j], ak = sa_b_in[8 + j], av = sa_b_in[16 + j];
            for (int i = 0; i < 8; i++) {
                float xi = Q[f * 8 + i];
                aq += xi * sa_w_in[j * 8 + i];
                ak += xi * sa_w_in[(8 + j) * 8 + i];
                av += xi * sa_w_in[(16 + j) * 8 + i];
            }
            qh[f][j] = aq; kh[f][j] = ak; vh[f][j] = av;
        }

    // 2-head attention, Dh=4, scale 1/sqrt(4)=0.5
    float ctx[4][8];
    for (int h = 0; h < 2; h++)
        for (int l = 0; l < 4; l++) {
            float sc[4], mx = -1e30f;
            for (int m = 0; m < 4; m++) {
                float s = 0.f;
                for (int d = 0; d < 4; d++) s += qh[l][h * 4 + d] * kh[m][h * 4 + d];
                sc[m] = s * 0.5f;
                mx = fmaxf(mx, sc[m]);
            }
            float den = 0.f;
            for (int m = 0; m < 4; m++) { sc[m] = expf(sc[m] - mx); den += sc[m]; }
            for (int d = 0; d < 4; d++) {
                float a = 0.f;
                for (int m = 0; m < 4; m++) a += sc[m] * vh[m][h * 4 + d];
                ctx[l][h * 4 + d] = a / den;
            }
        }

    float qupd[4][8];
    for (int f = 0; f < 4; f++)
        for (int e = 0; e < 8; e++) {
            float a = sa_b_out[e];
            for (int j = 0; j < 8; j++) a += ctx[f][j] * sa_w_out[e * 8 + j];
            qupd[f][e] = a;
        }

    // cross-attn q projection, pre-scaled by 0.5 (= 1/sqrt(Dh))
    float qc[4][8];
    for (int f = 0; f < 4; f++)
        for (int j = 0; j < 8; j++) {
            float a = ca_b_in[j];
            for (int e = 0; e < 8; e++) a += qupd[f][e] * ca_w_in[j * 8 + e];
            qc[f][j] = 0.5f * a;
        }

    // fold with ca_wk: scores[p][s] = bfold[p] + sum_i x[s][i] * wfold[p][i]
    for (int h = 0; h < 2; h++)
        for (int f = 0; f < 4; f++) {
            int p = h * 4 + f;
            for (int i = 0; i < 8; i++) {
                float w = 0.f;
                for (int d = 0; d < 4; d++)
                    w += qc[f][h * 4 + d] * ca_w_in[(8 + h * 4 + d) * 8 + i];
                g_wfold[p * 8 + i] = w;
            }
            float bf = 0.f;
            for (int d = 0; d < 4; d++) bf += qc[f][h * 4 + d] * ca_b_in[8 + h * 4 + d];
            g_bfold[p] = bf;
        }
}

// ---------------------------------------------------------------------------
// Halving-exchange warp reduction: N register values per lane (N power of 2).
// After return: lane owns max(1, N/32) fully-reduced values.
//   N=64: lane holds V[0]=sum of idx 2*lane, V[1]=idx 2*lane+1
//   N=32: lane holds V[0]=idx lane
//   N=8 : all lanes in quad hold V[0]=idx (lane>>2)
//   N=4 : all lanes in octet hold V[0]=idx (lane>>3)
// ---------------------------------------------------------------------------
template <int N>
__device__ __forceinline__ void warp_fold_reduce(float* V, int lane) {
    int c = N;
#pragma unroll
    for (int o = 16; o >= 1; o >>= 1) {
        if (c > 1) {
            int half = c >> 1;
#pragma unroll
            for (int j = 0; j < half; j++) {
                float send = (lane & o) ? V[j] : V[j + half];
                float recv = __shfl_xor_sync(FULLMASK, send, o);
                V[j] = ((lane & o) ? V[j + half] : V[j]) + recv;
            }
            c = half;
        } else {
            V[0] += __shfl_xor_sync(FULLMASK, V[0], o);
        }
    }
}

// ---------------------------------------------------------------------------
// Main kernel: one CTA per batch element. 256 threads, 2 tokens per thread.
// ---------------------------------------------------------------------------
__global__ void __launch_bounds__(256)
afs_main_kernel(const float* __restrict__ x,
                const float* __restrict__ ca_w_in, const float* __restrict__ ca_b_in,
                const float* __restrict__ ca_w_out, const float* __restrict__ ca_b_out,
                const float* __restrict__ r_w1, const float* __restrict__ r_b1,
                const float* __restrict__ r_w2, const float* __restrict__ r_b2,
                float* __restrict__ out_head, float* __restrict__ out_sim)
{
    const int b = blockIdx.x;
    const int tid = threadIdx.x;
    const int lane = tid & 31;
    const int wid = tid >> 5;

    __shared__ float sWf[64], sBf[8];
    __shared__ float redS[8][8];    // per-warp exp-sum partials (8 score rows)
    __shared__ float redA[8][64];   // per-warp A partials
    __shared__ float redD[8][4];    // per-warp sim exp-sum partials
    __shared__ float redF[8][32];   // per-warp final-factor partials
    __shared__ float sQ[32];        // Q_cross [f][e]

    if (tid < 64) sWf[tid] = g_wfold[tid];
    if (tid >= 64 && tid < 72) sBf[tid - 64] = g_bfold[tid - 64];

    // load this block's x tile straight into registers (tokens s0=tid, s1=tid+256)
    const float4* X4 = reinterpret_cast<const float4*>(x + (size_t)b * 4096);
    float4 a0 = X4[tid * 2], a1 = X4[tid * 2 + 1];
    float4 c0 = X4[(tid + 256) * 2], c1 = X4[(tid + 256) * 2 + 1];
    float x0[8] = {a0.x, a0.y, a0.z, a0.w, a1.x, a1.y, a1.z, a1.w};
    float x1[8] = {c0.x, c0.y, c0.z, c0.w, c1.x, c1.y, c1.z, c1.w};

    __syncthreads();

    // --- scores -> exp -> per-thread sums + A partials (all registers) ---
    float e0[8], e1[8];
#pragma unroll
    for (int p = 0; p < 8; p++) {
        float s0 = sBf[p], s1 = sBf[p];
#pragma unroll
        for (int i = 0; i < 8; i++) {
            float w = sWf[p * 8 + i];
            s0 = fmaf(w, x0[i], s0);
            s1 = fmaf(w, x1[i], s1);
        }
        e0[p] = __expf(s0);
        e1[p] = __expf(s1);
    }

    float sums[8];
#pragma unroll
    for (int p = 0; p < 8; p++) sums[p] = e0[p] + e1[p];

    float A[64];
#pragma unroll
    for (int p = 0; p < 8; p++)
#pragma unroll
        for (int i = 0; i < 8; i++)
            A[p * 8 + i] = e0[p] * x0[i] + e1[p] * x1[i];

    warp_fold_reduce<8>(sums, lane);
    if ((lane & 3) == 0) redS[wid][lane >> 2] = sums[0];

    warp_fold_reduce<64>(A, lane);
    redA[wid][2 * lane]     = A[0];
    redA[wid][2 * lane + 1] = A[1];

    __syncthreads();

    // --- warp 0: ctx + Q_cross (tiny) ---
    if (wid == 0) {
        int f = lane >> 3, j = lane & 7;       // lane <-> (f, j)
        int h = j >> 2, p = h * 4 + f;
        float At[8];
#pragma unroll
        for (int i = 0; i < 8; i++) {
            float s = 0.f;
#pragma unroll
            for (int w = 0; w < 8; w++) s += redA[w][p * 8 + i];
            At[i] = s;
        }
        float den = 0.f;
#pragma unroll
        for (int w = 0; w < 8; w++) den += redS[w][p];

        float accv = 0.f;
#pragma unroll
        for (int i = 0; i < 8; i++) accv = fmaf(ca_w_in[(16 + j) * 8 + i], At[i], accv);
        float ctxv = accv / den + ca_b_in[16 + j];   // vh bias: sum(attn)=1

        // Q_cross[f][e=j] = b_out[e] + sum_jj ctx[f][jj]*w_out[e][jj]
        float q = ca_b_out[j];
#pragma unroll
        for (int jj = 0; jj < 8; jj++) {
            float cv = __shfl_sync(FULLMASK, ctxv, f * 8 + jj);
            q = fmaf(ca_w_out[j * 8 + jj], cv, q);
        }
        sQ[f * 8 + j] = q;
    }
    __syncthreads();

    // --- similarity (written raw), exp, per-thread FF + denom partials ---
    float ds[4];
    float FF[32];
    float* simbase = out_sim + (size_t)b * 2048;
#pragma unroll
    for (int f = 0; f < 4; f++) {
        float s0 = 0.f, s1 = 0.f;
#pragma unroll
        for (int e = 0; e < 8; e++) {
            float qe = sQ[f * 8 + e];
            s0 = fmaf(qe, x0[e], s0);
            s1 = fmaf(qe, x1[e], s1);
        }
        simbase[f * 512 + tid]       = s0;   // pre-softmax similarity output
        simbase[f * 512 + tid + 256] = s1;
        float es0 = __expf(s0), es1 = __expf(s1);
        ds[f] = es0 + es1;
#pragma unroll
        for (int e = 0; e < 8; e++)
            FF[f * 8 + e] = es0 * x0[e] + es1 * x1[e];
    }

    warp_fold_reduce<4>(ds, lane);
    if ((lane & 7) == 0) redD[wid][lane >> 3] = ds[0];

    warp_fold_reduce<32>(FF, lane);
    redF[wid][lane] = FF[0];

    __syncthreads();

    // --- warp 0: normalize final factors + regression head ---
    if (wid == 0) {
        float s = 0.f;
#pragma unroll
        for (int w = 0; w < 8; w++) s += redF[w][lane];
        int f = lane >> 3;
        float den = 0.f;
#pragma unroll
        for (int w = 0; w < 8; w++) den += redD[w][f];
        float fused = s / den;          // lane k holds fused[k], k = f*8+e

        float hval = (lane < 16) ? r_b1[lane] : 0.f;
#pragma unroll
        for (int k = 0; k < 32; k++) {
            float fk = __shfl_sync(FULLMASK, fused, k);
            if (lane < 16) hval = fmaf(r_w1[lane * 32 + k], fk, hval);
        }
        hval = fmaxf(hval, 0.f);
        float o = (lane < 16) ? hval * r_w2[lane] : 0.f;
#pragma unroll
        for (int off = 16; off >= 1; off >>= 1)
            o += __shfl_xor_sync(FULLMASK, o, off);
        if (lane == 0) out_head[b] = o + r_b2[0];
    }
}

// ---------------------------------------------------------------------------
extern "C" void kernel_launch(void* const* d_in, const int* in_sizes, int n_in,
                              void* d_out, int out_size)
{
    const float* x        = (const float*)d_in[0];
    const float* Q        = (const float*)d_in[1];
    const float* sa_w_in  = (const float*)d_in[2];
    const float* sa_b_in  = (const float*)d_in[3];
    const float* sa_w_out = (const float*)d_in[4];
    const float* sa_b_out = (const float*)d_in[5];
    const float* ca_w_in  = (const float*)d_in[6];
    const float* ca_b_in  = (const float*)d_in[7];
    const float* ca_w_out = (const float*)d_in[8];
    const float* ca_b_out = (const float*)d_in[9];
    const float* r_w1     = (const float*)d_in[10];
    const float* r_b1     = (const float*)d_in[11];
    const float* r_w2     = (const float*)d_in[12];
    const float* r_b2     = (const float*)d_in[13];

    int B = in_sizes[0] / (512 * 8);

    float* out = (float*)d_out;
    float* out_head = out;       // (out, similarity) tuple order: out first
    float* out_sim  = out + B;   // then [B, 4, 512] similarity

    precompute_kernel<<<1, 32>>>(Q, sa_w_in, sa_b_in, sa_w_out, sa_b_out,
                                 ca_w_in, ca_b_in);
    afs_main_kernel<<<B, 256>>>(x, ca_w_in, ca_b_in, ca_w_out, ca_b_out,
                                r_w1, r_b1, r_w2, r_b2, out_head, out_sim);
}

// round 2
// speedup vs baseline: 1.7208x; 1.7208x over previous
#include <cuda_runtime.h>
#include <cstdint>

// Shapes fixed by the problem: B=16384, S=512, F=4, E=8, heads=2, Dh=4, H=16
#define FULLMASK 0xFFFFFFFFu

// Batch-invariant folded weights: [0:64) = wfold[p][i], [64:72) = bfold[p]
__device__ float g_fold[72];
__constant__ float c_fold[72];

// ---------------------------------------------------------------------------
// Pre-kernel: self-attention over Q (batch invariant) + fold cross-attn q/k.
// ---------------------------------------------------------------------------
__global__ void precompute_kernel(const float* __restrict__ Q,
                                  const float* __restrict__ sa_w_in,
                                  const float* __restrict__ sa_b_in,
                                  const float* __restrict__ sa_w_out,
                                  const float* __restrict__ sa_b_out,
                                  const float* __restrict__ ca_w_in,
                                  const float* __restrict__ ca_b_in)
{
    if (threadIdx.x != 0) return;

    // qkv projections of Q [4,8]; packed weight rows: q=0..7, k=8..15, v=16..23
    float qh[4][8], kh[4][8], vh[4][8];
    for (int f = 0; f < 4; f++)
        for (int j = 0; j < 8; j++) {
            float aq = sa_b_in[j], ak = sa_b_in[8 + j], av = sa_b_in[16 + j];
            for (int i = 0; i < 8; i++) {
                float xi = Q[f * 8 + i];
                aq += xi * sa_w_in[j * 8 + i];
                ak += xi * sa_w_in[(8 + j) * 8 + i];
                av += xi * sa_w_in[(16 + j) * 8 + i];
            }
            qh[f][j] = aq; kh[f][j] = ak; vh[f][j] = av;
        }

    // 2-head attention, Dh=4, scale 1/sqrt(4)=0.5
    float ctx[4][8];
    for (int h = 0; h < 2; h++)
        for (int l = 0; l < 4; l++) {
            float sc[4], mx = -1e30f;
            for (int m = 0; m < 4; m++) {
                float s = 0.f;
                for (int d = 0; d < 4; d++) s += qh[l][h * 4 + d] * kh[m][h * 4 + d];
                sc[m] = s * 0.5f;
                mx = fmaxf(mx, sc[m]);
            }
            float den = 0.f;
            for (int m = 0; m < 4; m++) { sc[m] = expf(sc[m] - mx); den += sc[m]; }
            for (int d = 0; d < 4; d++) {
                float a = 0.f;
                for (int m = 0; m < 4; m++) a += sc[m] * vh[m][h * 4 + d];
                ctx[l][h * 4 + d] = a / den;
            }
        }

    float qupd[4][8];
    for (int f = 0; f < 4; f++)
        for (int e = 0; e < 8; e++) {
            float a = sa_b_out[e];
            for (int j = 0; j < 8; j++) a += ctx[f][j] * sa_w_out[e * 8 + j];
            qupd[f][e] = a;
        }

    // cross-attn q projection, pre-scaled by 0.5 (= 1/sqrt(Dh))
    float qc[4][8];
    for (int f = 0; f < 4; f++)
        for (int j = 0; j < 8; j++) {
            float a = ca_b_in[j];
            for (int e = 0; e < 8; e++) a += qupd[f][e] * ca_w_in[j * 8 + e];
            qc[f][j] = 0.5f * a;
        }

    // fold with ca_wk: scores[p][s] = bfold[p] + sum_i x[s][i] * wfold[p][i]
    for (int h = 0; h < 2; h++)
        for (int f = 0; f < 4; f++) {
            int p = h * 4 + f;
            for (int i = 0; i < 8; i++) {
                float w = 0.f;
                for (int d = 0; d < 4; d++)
                    w += qc[f][h * 4 + d] * ca_w_in[(8 + h * 4 + d) * 8 + i];
                g_fold[p * 8 + i] = w;
            }
            float bf = 0.f;
            for (int d = 0; d < 4; d++) bf += qc[f][h * 4 + d] * ca_b_in[8 + h * 4 + d];
            g_fold[64 + p] = bf;
        }
}

// ---------------------------------------------------------------------------
// Halving-exchange warp reduction: N register values per lane (N power of 2).
// After return: lane owns max(1, N/32) fully-reduced values.
//   N=64: lane holds V[0]=sum of idx 2*lane, V[1]=idx 2*lane+1
//   N=32: lane holds V[0]=idx lane
//   N=8 : all lanes in quad hold V[0]=idx (lane>>2)
//   N=4 : all lanes in octet hold V[0]=idx (lane>>3)
// ---------------------------------------------------------------------------
template <int N>
__device__ __forceinline__ void warp_fold_reduce(float* V, int lane) {
    int c = N;
#pragma unroll
    for (int o = 16; o >= 1; o >>= 1) {
        if (c > 1) {
            int half = c >> 1;
#pragma unroll
            for (int j = 0; j < half; j++) {
                float send = (lane & o) ? V[j] : V[j + half];
                float recv = __shfl_xor_sync(FULLMASK, send, o);
                V[j] = ((lane & o) ? V[j + half] : V[j]) + recv;
            }
            c = half;
        } else {
            V[0] += __shfl_xor_sync(FULLMASK, V[0], o);
        }
    }
}

// ---------------------------------------------------------------------------
// Main kernel: one CTA per batch element. 128 threads, 4 tokens per thread.
// ---------------------------------------------------------------------------
__global__ void __launch_bounds__(128, 3)
afs_main_kernel(const float* __restrict__ x,
                const float* __restrict__ ca_w_in, const float* __restrict__ ca_b_in,
                const float* __restrict__ ca_w_out, const float* __restrict__ ca_b_out,
                const float* __restrict__ r_w1, const float* __restrict__ r_b1,
                const float* __restrict__ r_w2, const float* __restrict__ r_b2,
                float* __restrict__ out_head, float* __restrict__ out_sim)
{
    const int b = blockIdx.x;
    const int tid = threadIdx.x;
    const int lane = tid & 31;
    const int wid = tid >> 5;

    __shared__ __align__(16) float redA[4][64];   // per-warp A partials
    __shared__ float redS[4][8];                  // per-warp exp-sum partials
    __shared__ __align__(16) float redF[4][32];   // per-warp final-factor partials
    __shared__ float redD[4][4];                  // per-warp sim exp-sum partials
    __shared__ __align__(16) float sQ[32];        // Q_cross [f][e]

    // load this block's x tile straight into registers; token t_k = tid + 128*k
    const float4* X4 = reinterpret_cast<const float4*>(x + (size_t)b * 4096);
    float xr[4][8];
#pragma unroll
    for (int t = 0; t < 4; t++) {
        float4 u0 = X4[(tid + 128 * t) * 2];
        float4 u1 = X4[(tid + 128 * t) * 2 + 1];
        xr[t][0] = u0.x; xr[t][1] = u0.y; xr[t][2] = u0.z; xr[t][3] = u0.w;
        xr[t][4] = u1.x; xr[t][5] = u1.y; xr[t][6] = u1.z; xr[t][7] = u1.w;
    }

    // --- scores -> exp -> per-thread sums + A partials (all registers) ---
    float A[64], sums[8];
#pragma unroll
    for (int p = 0; p < 8; p++) {
        float bf = c_fold[64 + p];
        float s0 = bf, s1 = bf, s2 = bf, s3 = bf;
#pragma unroll
        for (int i = 0; i < 8; i++) {
            float w = c_fold[p * 8 + i];
            s0 = fmaf(w, xr[0][i], s0);
            s1 = fmaf(w, xr[1][i], s1);
            s2 = fmaf(w, xr[2][i], s2);
            s3 = fmaf(w, xr[3][i], s3);
        }
        float e0 = __expf(s0), e1 = __expf(s1), e2 = __expf(s2), e3 = __expf(s3);
        sums[p] = (e0 + e1) + (e2 + e3);
#pragma unroll
        for (int i = 0; i < 8; i++)
            A[p * 8 + i] = fmaf(e3, xr[3][i],
                           fmaf(e2, xr[2][i],
                           fmaf(e1, xr[1][i], e0 * xr[0][i])));
    }

    warp_fold_reduce<8>(sums, lane);
    if ((lane & 3) == 0) redS[wid][lane >> 2] = sums[0];

    warp_fold_reduce<64>(A, lane);
    reinterpret_cast<float2*>(redA[wid])[lane] = make_float2(A[0], A[1]);

    __syncthreads();

    // --- warp 0: ctx + Q_cross (tiny) ---
    if (wid == 0) {
        int f = lane >> 3, j = lane & 7;       // lane <-> (f, j)
        int h = j >> 2, p = h * 4 + f;
        float At[8];
#pragma unroll
        for (int i = 0; i < 8; i++) At[i] = 0.f;
        float den = 0.f;
#pragma unroll
        for (int w = 0; w < 4; w++) {
            const float4* r4 = reinterpret_cast<const float4*>(&redA[w][p * 8]);
            float4 v0 = r4[0], v1 = r4[1];
            At[0] += v0.x; At[1] += v0.y; At[2] += v0.z; At[3] += v0.w;
            At[4] += v1.x; At[5] += v1.y; At[6] += v1.z; At[7] += v1.w;
            den += redS[w][p];
        }

        float accv = 0.f;
#pragma unroll
        for (int i = 0; i < 8; i++) accv = fmaf(ca_w_in[(16 + j) * 8 + i], At[i], accv);
        float ctxv = accv / den + ca_b_in[16 + j];   // vh bias: sum(attn)=1

        // Q_cross[f][e=j] = b_out[e] + sum_jj ctx[f][jj]*w_out[e][jj]
        float q = ca_b_out[j];
#pragma unroll
        for (int jj = 0; jj < 8; jj++) {
            float cv = __shfl_sync(FULLMASK, ctxv, f * 8 + jj);
            q = fmaf(ca_w_out[j * 8 + jj], cv, q);
        }
        sQ[f * 8 + j] = q;
    }
    __syncthreads();

    // --- similarity (written raw), exp, per-thread FF + denom partials ---
    float ds[4];
    float FF[32];
    const float4* sQ4 = reinterpret_cast<const float4*>(sQ);
    float* simbase = out_sim + (size_t)b * 2048;
#pragma unroll
    for (int f = 0; f < 4; f++) {
        float4 qa = sQ4[f * 2], qb = sQ4[f * 2 + 1];
        float qf[8] = {qa.x, qa.y, qa.z, qa.w, qb.x, qb.y, qb.z, qb.w};
        float s0 = 0.f, s1 = 0.f, s2 = 0.f, s3 = 0.f;
#pragma unroll
        for (int i = 0; i < 8; i++) {
            s0 = fmaf(qf[i], xr[0][i], s0);
            s1 = fmaf(qf[i], xr[1][i], s1);
            s2 = fmaf(qf[i], xr[2][i], s2);
            s3 = fmaf(qf[i], xr[3][i], s3);
        }
        simbase[f * 512 + tid]       = s0;   // pre-softmax similarity output
        simbase[f * 512 + tid + 128] = s1;
        simbase[f * 512 + tid + 256] = s2;
        simbase[f * 512 + tid + 384] = s3;
        float e0 = __expf(s0), e1 = __expf(s1), e2 = __expf(s2), e3 = __expf(s3);
        ds[f] = (e0 + e1) + (e2 + e3);
#pragma unroll
        for (int i = 0; i < 8; i++)
            FF[f * 8 + i] = fmaf(e3, xr[3][i],
                            fmaf(e2, xr[2][i],
                            fmaf(e1, xr[1][i], e0 * xr[0][i])));
    }

    warp_fold_reduce<4>(ds, lane);
    if ((lane & 7) == 0) redD[wid][lane >> 3] = ds[0];

    warp_fold_reduce<32>(FF, lane);
    redF[wid][lane] = FF[0];

    __syncthreads();

    // --- warp 0: normalize final factors + regression head ---
    if (wid == 0) {
        float s = 0.f;
#pragma unroll
        for (int w = 0; w < 4; w++) s += redF[w][lane];
        int f = lane >> 3;
        float den = 0.f;
#pragma unroll
        for (int w = 0; w < 4; w++) den += redD[w][f];
        float fused = s / den;          // lane k holds fused[k], k = f*8+e

        float hval = (lane < 16) ? r_b1[lane] : 0.f;
#pragma unroll
        for (int k = 0; k < 32; k++) {
            float fk = __shfl_sync(FULLMASK, fused, k);
            if (lane < 16) hval = fmaf(r_w1[lane * 32 + k], fk, hval);
        }
        hval = fmaxf(hval, 0.f);
        float o = (lane < 16) ? hval * r_w2[lane] : 0.f;
#pragma unroll
        for (int off = 16; off >= 1; off >>= 1)
            o += __shfl_xor_sync(FULLMASK, o, off);
        if (lane == 0) out_head[b] = o + r_b2[0];
    }
}

// ---------------------------------------------------------------------------
extern "C" void kernel_launch(void* const* d_in, const int* in_sizes, int n_in,
                              void* d_out, int out_size)
{
    const float* x        = (const float*)d_in[0];
    const float* Q        = (const float*)d_in[1];
    const float* sa_w_in  = (const float*)d_in[2];
    const float* sa_b_in  = (const float*)d_in[3];
    const float* sa_w_out = (const float*)d_in[4];
    const float* sa_b_out = (const float*)d_in[5];
    const float* ca_w_in  = (const float*)d_in[6];
    const float* ca_b_in  = (const float*)d_in[7];
    const float* ca_w_out = (const float*)d_in[8];
    const float* ca_b_out = (const float*)d_in[9];
    const float* r_w1     = (const float*)d_in[10];
    const float* r_b1     = (const float*)d_in[11];
    const float* r_w2     = (const float*)d_in[12];
    const float* r_b2     = (const float*)d_in[13];

    int B = in_sizes[0] / (512 * 8);

    float* out = (float*)d_out;
    float* out_head = out;       // (out, similarity) tuple order: out first
    float* out_sim  = out + B;   // then [B, 4, 512] similarity

    precompute_kernel<<<1, 32>>>(Q, sa_w_in, sa_b_in, sa_w_out, sa_b_out,
                                 ca_w_in, ca_b_in);

    // copy folded weights (device global) into constant bank for the main kernel
    void* pFold = nullptr;
    cudaGetSymbolAddress(&pFold, g_fold);
    cudaMemcpyToSymbolAsync(c_fold, pFold, 72 * sizeof(float), 0,
                            cudaMemcpyDeviceToDevice, 0);

    afs_main_kernel<<<B, 128>>>(x, ca_w_in, ca_b_in, ca_w_out, ca_b_out,
                                r_w1, r_b1, r_w2, r_b2, out_head, out_sim);
}

// round 3
// speedup vs baseline: 1.8703x; 1.0869x over previous
#include <cuda_runtime.h>
#include <cstdint>

// Shapes fixed by the problem: B=16384, S=512, F=4, E=8, heads=2, Dh=4, H=16
#define FULLMASK 0xFFFFFFFFu
typedef unsigned long long ull;   // packed f32x2 (lo, hi) in an aligned reg pair

__device__ __forceinline__ ull pk2(float a, float b) {
    ull r; asm("mov.b64 %0, {%1, %2};" : "=l"(r) : "f"(a), "f"(b)); return r;
}
__device__ __forceinline__ void upk2(ull v, float& a, float& b) {
    asm("mov.b64 {%0, %1}, %2;" : "=f"(a), "=f"(b) : "l"(v));
}
__device__ __forceinline__ ull fma2(ull a, ull b, ull c) {
    ull d; asm("fma.rn.f32x2 %0, %1, %2, %3;" : "=l"(d) : "l"(a), "l"(b), "l"(c)); return d;
}
__device__ __forceinline__ ull add2(ull a, ull b) {
    ull d; asm("add.rn.f32x2 %0, %1, %2;" : "=l"(d) : "l"(a), "l"(b)); return d;
}

// Batch-invariant folded weights: [0:64) = wfold[p][i], [64:72) = bfold[p]
__device__ float g_fold[72];
__constant__ __align__(16) float c_fold[72];

// ---------------------------------------------------------------------------
// Pre-kernel: self-attention over Q (batch invariant) + fold cross-attn q/k.
// ---------------------------------------------------------------------------
__global__ void precompute_kernel(const float* __restrict__ Q,
                                  const float* __restrict__ sa_w_in,
                                  const float* __restrict__ sa_b_in,
                                  const float* __restrict__ sa_w_out,
                                  const float* __restrict__ sa_b_out,
                                  const float* __restrict__ ca_w_in,
                                  const float* __restrict__ ca_b_in)
{
    if (threadIdx.x != 0) return;

    float qh[4][8], kh[4][8], vh[4][8];
    for (int f = 0; f < 4; f++)
        for (int j = 0; j < 8; j++) {
            float aq = sa_b_in[j], ak = sa_b_in[8 + j], av = sa_b_in[16 + j];
            for (int i = 0; i < 8; i++) {
                float xi = Q[f * 8 + i];
                aq += xi * sa_w_in[j * 8 + i];
                ak += xi * sa_w_in[(8 + j) * 8 + i];
                av += xi * sa_w_in[(16 + j) * 8 + i];
            }
            qh[f][j] = aq; kh[f][j] = ak; vh[f][j] = av;
        }

    float ctx[4][8];
    for (int h = 0; h < 2; h++)
        for (int l = 0; l < 4; l++) {
            float sc[4], mx = -1e30f;
            for (int m = 0; m < 4; m++) {
                float s = 0.f;
                for (int d = 0; d < 4; d++) s += qh[l][h * 4 + d] * kh[m][h * 4 + d];
                sc[m] = s * 0.5f;
                mx = fmaxf(mx, sc[m]);
            }
            float den = 0.f;
            for (int m = 0; m < 4; m++) { sc[m] = expf(sc[m] - mx); den += sc[m]; }
            for (int d = 0; d < 4; d++) {
                float a = 0.f;
                for (int m = 0; m < 4; m++) a += sc[m] * vh[m][h * 4 + d];
                ctx[l][h * 4 + d] = a / den;
            }
        }

    float qupd[4][8];
    for (int f = 0; f < 4; f++)
        for (int e = 0; e < 8; e++) {
            float a = sa_b_out[e];
            for (int j = 0; j < 8; j++) a += ctx[f][j] * sa_w_out[e * 8 + j];
            qupd[f][e] = a;
        }

    float qc[4][8];
    for (int f = 0; f < 4; f++)
        for (int j = 0; j < 8; j++) {
            float a = ca_b_in[j];
            for (int e = 0; e < 8; e++) a += qupd[f][e] * ca_w_in[j * 8 + e];
            qc[f][j] = 0.5f * a;
        }

    for (int h = 0; h < 2; h++)
        for (int f = 0; f < 4; f++) {
            int p = h * 4 + f;
            for (int i = 0; i < 8; i++) {
                float w = 0.f;
                for (int d = 0; d < 4; d++)
                    w += qc[f][h * 4 + d] * ca_w_in[(8 + h * 4 + d) * 8 + i];
                g_fold[p * 8 + i] = w;
            }
            float bf = 0.f;
            for (int d = 0; d < 4; d++) bf += qc[f][h * 4 + d] * ca_b_in[8 + h * 4 + d];
            g_fold[64 + p] = bf;
        }
}

// ---------------------------------------------------------------------------
// Halving-exchange warp reductions.
// Scalar (N=4): after return all lanes in octet hold idx (lane>>3).
// Packed (N=16 ull): after return lane holds packed idx (lane>>1), i.e. the
// scalar pair (2*(lane>>1), 2*(lane>>1)+1).
// ---------------------------------------------------------------------------
template <int N>
__device__ __forceinline__ void warp_fold_reduce(float* V, int lane) {
    int c = N;
#pragma unroll
    for (int o = 16; o >= 1; o >>= 1) {
        if (c > 1) {
            int half = c >> 1;
#pragma unroll
            for (int j = 0; j < half; j++) {
                float send = (lane & o) ? V[j] : V[j + half];
                float recv = __shfl_xor_sync(FULLMASK, send, o);
                V[j] = ((lane & o) ? V[j + half] : V[j]) + recv;
            }
            c = half;
        } else {
            V[0] += __shfl_xor_sync(FULLMASK, V[0], o);
        }
    }
}

template <int N>
__device__ __forceinline__ void warp_fold_reduce2(ull* V, int lane) {
    int c = N;
#pragma unroll
    for (int o = 16; o >= 1; o >>= 1) {
        if (c > 1) {
            int half = c >> 1;
#pragma unroll
            for (int j = 0; j < half; j++) {
                ull send = (lane & o) ? V[j] : V[j + half];
                ull recv = __shfl_xor_sync(FULLMASK, send, o);
                V[j] = add2((lane & o) ? V[j + half] : V[j], recv);
            }
            c = half;
        } else {
            V[0] = add2(V[0], __shfl_xor_sync(FULLMASK, V[0], o));
        }
    }
}

// ---------------------------------------------------------------------------
// Main kernel: one CTA per batch element. 128 threads, 4 tokens per thread.
// All heavy FMA loops are packed f32x2 over feature pairs.
// ---------------------------------------------------------------------------
__global__ void __launch_bounds__(128, 5)
afs_main_kernel(const float* __restrict__ x,
                const float* __restrict__ ca_w_in, const float* __restrict__ ca_b_in,
                const float* __restrict__ ca_w_out, const float* __restrict__ ca_b_out,
                const float* __restrict__ r_w1, const float* __restrict__ r_b1,
                const float* __restrict__ r_w2, const float* __restrict__ r_b2,
                float* __restrict__ out_head, float* __restrict__ out_sim)
{
    const int b = blockIdx.x;
    const int tid = threadIdx.x;
    const int lane = tid & 31;
    const int wid = tid >> 5;

    __shared__ __align__(16) float redA[4][64];   // per-warp A partials
    __shared__ float redS[4][8];                  // per-warp exp-sum partials
    __shared__ __align__(16) float redF[4][32];   // per-warp final-factor partials
    __shared__ float redD[4][4];                  // per-warp sim exp-sum partials
    __shared__ __align__(16) float sQ[32];        // Q_cross [f][e]

    // x tile into registers as packed feature pairs; token t_k = tid + 128*k
    const float4* X4 = reinterpret_cast<const float4*>(x + (size_t)b * 4096);
    ull x2[4][4];
#pragma unroll
    for (int t = 0; t < 4; t++) {
        float4 u0 = __ldcs(&X4[(tid + 128 * t) * 2]);
        float4 u1 = __ldcs(&X4[(tid + 128 * t) * 2 + 1]);
        x2[t][0] = pk2(u0.x, u0.y); x2[t][1] = pk2(u0.z, u0.w);
        x2[t][2] = pk2(u1.x, u1.y); x2[t][3] = pk2(u1.z, u1.w);
    }

    const ull* cw2 = reinterpret_cast<const ull*>(c_fold);   // [p*4+h] feature pairs

    // --- phase 1: scores -> exp -> A partials, p chunked in halves of 4 ---
#pragma unroll
    for (int c = 0; c < 2; c++) {
        ull A2[16];                                // [pp*4+h]
#pragma unroll
        for (int j = 0; j < 16; j++) A2[j] = 0ull;
        float sums[4] = {0.f, 0.f, 0.f, 0.f};

#pragma unroll
        for (int t = 0; t < 4; t++) {
#pragma unroll
            for (int pp = 0; pp < 4; pp++) {
                int p = 4 * c + pp;
                ull acc = fma2(cw2[p * 4 + 0], x2[t][0],
                          fma2(cw2[p * 4 + 1], x2[t][1],
                          fma2(cw2[p * 4 + 2], x2[t][2],
                          fma2(cw2[p * 4 + 3], x2[t][3], 0ull))));
                float slo, shi; upk2(acc, slo, shi);
                float e = __expf(slo + shi + c_fold[64 + p]);
                sums[pp] += e;
                ull e2 = pk2(e, e);
#pragma unroll
                for (int h = 0; h < 4; h++)
                    A2[pp * 4 + h] = fma2(e2, x2[t][h], A2[pp * 4 + h]);
            }
        }

        warp_fold_reduce2<16>(A2, lane);
        if (!(lane & 1))
            reinterpret_cast<ull*>(&redA[wid][32 * c])[lane >> 1] = A2[0];

        warp_fold_reduce<4>(sums, lane);
        if (!(lane & 7)) redS[wid][4 * c + (lane >> 3)] = sums[0];
    }

    __syncthreads();

    // --- warp 0: ctx + Q_cross (tiny) ---
    if (wid == 0) {
        int f = lane >> 3, j = lane & 7;       // lane <-> (f, j)
        int h = j >> 2, p = h * 4 + f;
        float At[8];
#pragma unroll
        for (int i = 0; i < 8; i++) At[i] = 0.f;
        float den = 0.f;
#pragma unroll
        for (int w = 0; w < 4; w++) {
            const float4* r4 = reinterpret_cast<const float4*>(&redA[w][p * 8]);
            float4 v0 = r4[0], v1 = r4[1];
            At[0] += v0.x; At[1] += v0.y; At[2] += v0.z; At[3] += v0.w;
            At[4] += v1.x; At[5] += v1.y; At[6] += v1.z; At[7] += v1.w;
            den += redS[w][p];
        }

        float accv = 0.f;
#pragma unroll
        for (int i = 0; i < 8; i++) accv = fmaf(ca_w_in[(16 + j) * 8 + i], At[i], accv);
        float ctxv = accv / den + ca_b_in[16 + j];   // vh bias: sum(attn)=1

        float q = ca_b_out[j];
#pragma unroll
        for (int jj = 0; jj < 8; jj++) {
            float cv = __shfl_sync(FULLMASK, ctxv, f * 8 + jj);
            q = fmaf(ca_w_out[j * 8 + jj], cv, q);
        }
        sQ[f * 8 + j] = q;
    }
    __syncthreads();

    // --- phase 2: similarity (raw out), exp, FF + denom partials ---
    const ull* sQ2 = reinterpret_cast<const ull*>(sQ);   // [f*4+h]
    float* simbase = out_sim + (size_t)b * 2048;
    ull FF2[16];                                         // [f*4+h]
#pragma unroll
    for (int j = 0; j < 16; j++) FF2[j] = 0ull;
    float ds[4] = {0.f, 0.f, 0.f, 0.f};

#pragma unroll
    for (int t = 0; t < 4; t++) {
#pragma unroll
        for (int f = 0; f < 4; f++) {
            ull acc = fma2(sQ2[f * 4 + 0], x2[t][0],
                      fma2(sQ2[f * 4 + 1], x2[t][1],
                      fma2(sQ2[f * 4 + 2], x2[t][2],
                      fma2(sQ2[f * 4 + 3], x2[t][3], 0ull))));
            float slo, shi; upk2(acc, slo, shi);
            float s = slo + shi;
            __stcs(&simbase[f * 512 + tid + 128 * t], s);   // pre-softmax similarity
            float e = __expf(s);
            ds[f] += e;
            ull e2 = pk2(e, e);
#pragma unroll
            for (int h = 0; h < 4; h++)
                FF2[f * 4 + h] = fma2(e2, x2[t][h], FF2[f * 4 + h]);
        }
    }

    warp_fold_reduce2<16>(FF2, lane);
    if (!(lane & 1))
        reinterpret_cast<ull*>(redF[wid])[lane >> 1] = FF2[0];

    warp_fold_reduce<4>(ds, lane);
    if (!(lane & 7)) redD[wid][lane >> 3] = ds[0];

    __syncthreads();

    // --- warp 0: normalize final factors + regression head ---
    if (wid == 0) {
        float s = 0.f;
#pragma unroll
        for (int w = 0; w < 4; w++) s += redF[w][lane];
        int f = lane >> 3;
        float den = 0.f;
#pragma unroll
        for (int w = 0; w < 4; w++) den += redD[w][f];
        float fused = s / den;          // lane k holds fused[k], k = f*8+e

        float hval = (lane < 16) ? r_b1[lane] : 0.f;
#pragma unroll
        for (int k = 0; k < 32; k++) {
            float fk = __shfl_sync(FULLMASK, fused, k);
            if (lane < 16) hval = fmaf(r_w1[lane * 32 + k], fk, hval);
        }
        hval = fmaxf(hval, 0.f);
        float o = (lane < 16) ? hval * r_w2[lane] : 0.f;
#pragma unroll
        for (int off = 16; off >= 1; off >>= 1)
            o += __shfl_xor_sync(FULLMASK, o, off);
        if (lane == 0) out_head[b] = o + r_b2[0];
    }
}

// ---------------------------------------------------------------------------
extern "C" void kernel_launch(void* const* d_in, const int* in_sizes, int n_in,
                              void* d_out, int out_size)
{
    const float* x        = (const float*)d_in[0];
    const float* Q        = (const float*)d_in[1];
    const float* sa_w_in  = (const float*)d_in[2];
    const float* sa_b_in  = (const float*)d_in[3];
    const float* sa_w_out = (const float*)d_in[4];
    const float* sa_b_out = (const float*)d_in[5];
    const float* ca_w_in  = (const float*)d_in[6];
    const float* ca_b_in  = (const float*)d_in[7];
    const float* ca_w_out = (const float*)d_in[8];
    const float* ca_b_out = (const float*)d_in[9];
    const float* r_w1     = (const float*)d_in[10];
    const float* r_b1     = (const float*)d_in[11];
    const float* r_w2     = (const float*)d_in[12];
    const float* r_b2     = (const float*)d_in[13];

    int B = in_sizes[0] / (512 * 8);

    float* out = (float*)d_out;
    float* out_head = out;       // (out, similarity) tuple order: out first
    float* out_sim  = out + B;   // then [B, 4, 512] similarity

    precompute_kernel<<<1, 32>>>(Q, sa_w_in, sa_b_in, sa_w_out, sa_b_out,
                                 ca_w_in, ca_b_in);

    // copy folded weights (device global) into constant bank for the main kernel
    void* pFold = nullptr;
    cudaGetSymbolAddress(&pFold, g_fold);
    cudaMemcpyToSymbolAsync(c_fold, pFold, 72 * sizeof(float), 0,
                            cudaMemcpyDeviceToDevice, 0);

    afs_main_kernel<<<B, 128>>>(x, ca_w_in, ca_b_in, ca_w_out, ca_b_out,
                                r_w1, r_b1, r_w2, r_b2, out_head, out_sim);
}

// round 6
// speedup vs baseline: 2.9361x; 1.5698x over previous
#include <cuda_runtime.h>
#include <cstdint>

// Shapes fixed by the problem: B=16384, S=512, F=4, E=8, heads=2, Dh=4, H=16
#define FULLMASK 0xFFFFFFFFu
typedef unsigned long long ull;   // packed f32x2 (lo, hi) in an aligned reg pair

__device__ __forceinline__ ull pk2(float a, float b) {
    ull r; asm("mov.b64 %0, {%1, %2};" : "=l"(r) : "f"(a), "f"(b)); return r;
}
__device__ __forceinline__ void upk2(ull v, float& a, float& b) {
    asm("mov.b64 {%0, %1}, %2;" : "=f"(a), "=f"(b) : "l"(v));
}
__device__ __forceinline__ ull fma2(ull a, ull b, ull c) {
    ull d; asm("fma.rn.f32x2 %0, %1, %2, %3;" : "=l"(d) : "l"(a), "l"(b), "l"(c)); return d;
}
__device__ __forceinline__ ull add2(ull a, ull b) {
    ull d; asm("add.rn.f32x2 %0, %1, %2;" : "=l"(d) : "l"(a), "l"(b)); return d;
}

// Batch-invariant folded weights: [0:64) = wfold[p][i], [64:72) = bfold[p]
__device__ float g_fold[72];
__constant__ __align__(16) float c_fold[72];

// ---------------------------------------------------------------------------
// Pre-kernel: self-attention over Q (batch invariant) + fold cross-attn q/k.
// ---------------------------------------------------------------------------
__global__ void precompute_kernel(const float* __restrict__ Q,
                                  const float* __restrict__ sa_w_in,
                                  const float* __restrict__ sa_b_in,
                                  const float* __restrict__ sa_w_out,
                                  const float* __restrict__ sa_b_out,
                                  const float* __restrict__ ca_w_in,
                                  const float* __restrict__ ca_b_in)
{
    if (threadIdx.x != 0) return;

    float qh[4][8], kh[4][8], vh[4][8];
    for (int f = 0; f < 4; f++)
        for (int j = 0; j < 8; j++) {
            float aq = sa_b_in[j], ak = sa_b_in[8 + j], av = sa_b_in[16 + j];
            for (int i = 0; i < 8; i++) {
                float xi = Q[f * 8 + i];
                aq += xi * sa_w_in[j * 8 + i];
                ak += xi * sa_w_in[(8 + j) * 8 + i];
                av += xi * sa_w_in[(16 + j) * 8 + i];
            }
            qh[f][j] = aq; kh[f][j] = ak; vh[f][j] = av;
        }

    float ctx[4][8];
    for (int h = 0; h < 2; h++)
        for (int l = 0; l < 4; l++) {
            float sc[4], mx = -1e30f;
            for (int m = 0; m < 4; m++) {
                float s = 0.f;
                for (int d = 0; d < 4; d++) s += qh[l][h * 4 + d] * kh[m][h * 4 + d];
                sc[m] = s * 0.5f;
                mx = fmaxf(mx, sc[m]);
            }
            float den = 0.f;
            for (int m = 0; m < 4; m++) { sc[m] = expf(sc[m] - mx); den += sc[m]; }
            for (int d = 0; d < 4; d++) {
                float a = 0.f;
                for (int m = 0; m < 4; m++) a += sc[m] * vh[m][h * 4 + d];
                ctx[l][h * 4 + d] = a / den;
            }
        }

    float qupd[4][8];
    for (int f = 0; f < 4; f++)
        for (int e = 0; e < 8; e++) {
            float a = sa_b_out[e];
            for (int j = 0; j < 8; j++) a += ctx[f][j] * sa_w_out[e * 8 + j];
            qupd[f][e] = a;
        }

    float qc[4][8];
    for (int f = 0; f < 4; f++)
        for (int j = 0; j < 8; j++) {
            float a = ca_b_in[j];
            for (int e = 0; e < 8; e++) a += qupd[f][e] * ca_w_in[j * 8 + e];
            qc[f][j] = 0.5f * a;
        }

    for (int h = 0; h < 2; h++)
        for (int f = 0; f < 4; f++) {
            int p = h * 4 + f;
            for (int i = 0; i < 8; i++) {
                float w = 0.f;
                for (int d = 0; d < 4; d++)
                    w += qc[f][h * 4 + d] * ca_w_in[(8 + h * 4 + d) * 8 + i];
                g_fold[p * 8 + i] = w;
            }
            float bf = 0.f;
            for (int d = 0; d < 4; d++) bf += qc[f][h * 4 + d] * ca_b_in[8 + h * 4 + d];
            g_fold[64 + p] = bf;
        }
}

// ---------------------------------------------------------------------------
// Halving-exchange warp reductions.
// Scalar (N=4): after return all lanes in octet hold idx (lane>>3).
// Packed (N=16 ull): after return lane holds packed idx (lane>>1).
// ---------------------------------------------------------------------------
template <int N>
__device__ __forceinline__ void warp_fold_reduce(float* V, int lane) {
    int c = N;
#pragma unroll
    for (int o = 16; o >= 1; o >>= 1) {
        if (c > 1) {
            int half = c >> 1;
#pragma unroll
            for (int j = 0; j < half; j++) {
                float send = (lane & o) ? V[j] : V[j + half];
                float recv = __shfl_xor_sync(FULLMASK, send, o);
                V[j] = ((lane & o) ? V[j + half] : V[j]) + recv;
            }
            c = half;
        } else {
            V[0] += __shfl_xor_sync(FULLMASK, V[0], o);
        }
    }
}

template <int N>
__device__ __forceinline__ void warp_fold_reduce2(ull* V, int lane) {
    int c = N;
#pragma unroll
    for (int o = 16; o >= 1; o >>= 1) {
        if (c > 1) {
            int half = c >> 1;
#pragma unroll
            for (int j = 0; j < half; j++) {
                ull send = (lane & o) ? V[j] : V[j + half];
                ull recv = __shfl_xor_sync(FULLMASK, send, o);
                V[j] = add2((lane & o) ? V[j + half] : V[j], recv);
            }
            c = half;
        } else {
            V[0] = add2(V[0], __shfl_xor_sync(FULLMASK, V[0], o));
        }
    }
}

// ---------------------------------------------------------------------------
// Main kernel: one CTA per batch element. 64 threads, 8 tokens per thread.
// All heavy FMA loops are packed f32x2 over feature pairs. The per-warp
// reduction cost is fixed, so fewer warps = less MIO (L1TEX) pressure.
// ---------------------------------------------------------------------------
__global__ void __launch_bounds__(64, 8)
afs_main_kernel(const float* __restrict__ x,
                const float* __restrict__ ca_w_in, const float* __restrict__ ca_b_in,
                const float* __restrict__ ca_w_out, const float* __restrict__ ca_b_out,
                const float* __restrict__ r_w1, const float* __restrict__ r_b1,
                const float* __restrict__ r_w2, const float* __restrict__ r_b2,
                float* __restrict__ out_head, float* __restrict__ out_sim)
{
    const int b = blockIdx.x;
    const int tid = threadIdx.x;
    const int lane = tid & 31;
    const int wid = tid >> 5;

    __shared__ __align__(16) float redA[2][64];   // per-warp A partials
    __shared__ float redS[2][8];                  // per-warp exp-sum partials
    __shared__ __align__(16) float redF[2][32];   // per-warp final-factor partials
    __shared__ float redD[2][4];                  // per-warp sim exp-sum partials
    __shared__ __align__(16) float sQ[32];        // Q_cross [f][e]

    // x tile into registers as packed feature pairs; token t_k = tid + 64*k
    const float4* X4 = reinterpret_cast<const float4*>(x + (size_t)b * 4096);
    ull x2[8][4];
#pragma unroll
    for (int t = 0; t < 8; t++) {
        float4 u0 = __ldcs(&X4[(tid + 64 * t) * 2]);
        float4 u1 = __ldcs(&X4[(tid + 64 * t) * 2 + 1]);
        x2[t][0] = pk2(u0.x, u0.y); x2[t][1] = pk2(u0.z, u0.w);
        x2[t][2] = pk2(u1.x, u1.y); x2[t][3] = pk2(u1.z, u1.w);
    }

    const ull* cw2 = reinterpret_cast<const ull*>(c_fold);   // [p*4+h] feature pairs

    // --- phase 1: scores -> exp -> A partials, p chunked in halves of 4 ---
#pragma unroll
    for (int c = 0; c < 2; c++) {
        ull A2[16];                                // [pp*4+h]
#pragma unroll
        for (int j = 0; j < 16; j++) A2[j] = 0ull;
        float sums[4] = {0.f, 0.f, 0.f, 0.f};

#pragma unroll
        for (int t = 0; t < 8; t++) {
#pragma unroll
            for (int pp = 0; pp < 4; pp++) {
                int p = 4 * c + pp;
                ull acc = fma2(cw2[p * 4 + 0], x2[t][0],
                          fma2(cw2[p * 4 + 1], x2[t][1],
                          fma2(cw2[p * 4 + 2], x2[t][2],
                          fma2(cw2[p * 4 + 3], x2[t][3], 0ull))));
                float slo, shi; upk2(acc, slo, shi);
                float e = __expf(slo + shi + c_fold[64 + p]);
                sums[pp] += e;
                ull e2 = pk2(e, e);
#pragma unroll
                for (int h = 0; h < 4; h++)
                    A2[pp * 4 + h] = fma2(e2, x2[t][h], A2[pp * 4 + h]);
            }
        }

        warp_fold_reduce2<16>(A2, lane);
        if (!(lane & 1))
            reinterpret_cast<ull*>(&redA[wid][32 * c])[lane >> 1] = A2[0];

        warp_fold_reduce<4>(sums, lane);
        if (!(lane & 7)) redS[wid][4 * c + (lane >> 3)] = sums[0];
    }

    __syncthreads();

    // --- warp 0: ctx + Q_cross (tiny) ---
    if (wid == 0) {
        int f = lane >> 3, j = lane & 7;       // lane <-> (f, j)
        int h = j >> 2, p = h * 4 + f;
        float At[8];
#pragma unroll
        for (int i = 0; i < 8; i++) At[i] = 0.f;
        float den = 0.f;
#pragma unroll
        for (int w = 0; w < 2; w++) {
            const float4* r4 = reinterpret_cast<const float4*>(&redA[w][p * 8]);
            float4 v0 = r4[0], v1 = r4[1];
            At[0] += v0.x; At[1] += v0.y; At[2] += v0.z; At[3] += v0.w;
            At[4] += v1.x; At[5] += v1.y; At[6] += v1.z; At[7] += v1.w;
            den += redS[w][p];
        }

        float accv = 0.f;
#pragma unroll
        for (int i = 0; i < 8; i++) accv = fmaf(ca_w_in[(16 + j) * 8 + i], At[i], accv);
        float ctxv = accv / den + ca_b_in[16 + j];   // vh bias: sum(attn)=1

        float q = ca_b_out[j];
#pragma unroll
        for (int jj = 0; jj < 8; jj++) {
            float cv = __shfl_sync(FULLMASK, ctxv, f * 8 + jj);
            q = fmaf(ca_w_out[j * 8 + jj], cv, q);
        }
        sQ[f * 8 + j] = q;
    }
    __syncthreads();

    // --- phase 2: similarity (raw out), exp, FF + denom partials ---
    const ull* sQ2 = reinterpret_cast<const ull*>(sQ);   // [f*4+h]
    float* simbase = out_sim + (size_t)b * 2048;
    ull FF2[16];                                         // [f*4+h]
#pragma unroll
    for (int j = 0; j < 16; j++) FF2[j] = 0ull;
    float ds[4] = {0.f, 0.f, 0.f, 0.f};

#pragma unroll
    for (int t = 0; t < 8; t++) {
#pragma unroll
        for (int f = 0; f < 4; f++) {
            ull acc = fma2(sQ2[f * 4 + 0], x2[t][0],
                      fma2(sQ2[f * 4 + 1], x2[t][1],
                      fma2(sQ2[f * 4 + 2], x2[t][2],
                      fma2(sQ2[f * 4 + 3], x2[t][3], 0ull))));
            float slo, shi; upk2(acc, slo, shi);
            float s = slo + shi;
            __stcs(&simbase[f * 512 + tid + 64 * t], s);   // pre-softmax similarity
            float e = __expf(s);
            ds[f] += e;
            ull e2 = pk2(e, e);
#pragma unroll
            for (int h = 0; h < 4; h++)
                FF2[f * 4 + h] = fma2(e2, x2[t][h], FF2[f * 4 + h]);
        }
    }

    warp_fold_reduce2<16>(FF2, lane);
    if (!(lane & 1))
        reinterpret_cast<ull*>(redF[wid])[lane >> 1] = FF2[0];

    warp_fold_reduce<4>(ds, lane);
    if (!(lane & 7)) redD[wid][lane >> 3] = ds[0];

    __syncthreads();

    // --- warp 0: normalize final factors + regression head ---
    if (wid == 0) {
        float s = 0.f;
#pragma unroll
        for (int w = 0; w < 2; w++) s += redF[w][lane];
        int f = lane >> 3;
        float den = 0.f;
#pragma unroll
        for (int w = 0; w < 2; w++) den += redD[w][f];
        float fused = s / den;          // lane k holds fused[k], k = f*8+e

        float hval = (lane < 16) ? r_b1[lane] : 0.f;
#pragma unroll
        for (int k = 0; k < 32; k++) {
            float fk = __shfl_sync(FULLMASK, fused, k);
            if (lane < 16) hval = fmaf(r_w1[lane * 32 + k], fk, hval);
        }
        hval = fmaxf(hval, 0.f);
        float o = (lane < 16) ? hval * r_w2[lane] : 0.f;
#pragma unroll
        for (int off = 16; off >= 1; off >>= 1)
            o += __shfl_xor_sync(FULLMASK, o, off);
        if (lane == 0) out_head[b] = o + r_b2[0];
    }
}

// ---------------------------------------------------------------------------
extern "C" void kernel_launch(void* const* d_in, const int* in_sizes, int n_in,
                              void* d_out, int out_size)
{
    const float* x        = (const float*)d_in[0];
    const float* Q        = (const float*)d_in[1];
    const float* sa_w_in  = (const float*)d_in[2];
    const float* sa_b_in  = (const float*)d_in[3];
    const float* sa_w_out = (const float*)d_in[4];
    const float* sa_b_out = (const float*)d_in[5];
    const float* ca_w_in  = (const float*)d_in[6];
    const float* ca_b_in  = (const float*)d_in[7];
    const float* ca_w_out = (const float*)d_in[8];
    const float* ca_b_out = (const float*)d_in[9];
    const float* r_w1     = (const float*)d_in[10];
    const float* r_b1     = (const float*)d_in[11];
    const float* r_w2     = (const float*)d_in[12];
    const float* r_b2     = (const float*)d_in[13];

    int B = in_sizes[0] / (512 * 8);

    float* out = (float*)d_out;
    float* out_head = out;       // (out, similarity) tuple order: out first
    float* out_sim  = out + B;   // then [B, 4, 512] similarity

    precompute_kernel<<<1, 32>>>(Q, sa_w_in, sa_b_in, sa_w_out, sa_b_out,
                                 ca_w_in, ca_b_in);

    // copy folded weights (device global) into constant bank for the main kernel
    void* pFold = nullptr;
    cudaGetSymbolAddress(&pFold, g_fold);
    cudaMemcpyToSymbolAsync(c_fold, pFold, 72 * sizeof(float), 0,
                            cudaMemcpyDeviceToDevice, 0);

    afs_main_kernel<<<B, 64>>>(x, ca_w_in, ca_b_in, ca_w_out, ca_b_out,
                               r_w1, r_b1, r_w2, r_b2, out_head, out_sim);
}

// round 7
// speedup vs baseline: 4.1577x; 1.4161x over previous
#include <cuda_runtime.h>
#include <cstdint>

// Shapes fixed by the problem: B=16384, S=512, F=4, E=8, heads=2, Dh=4, H=16
#define FULLMASK 0xFFFFFFFFu
typedef unsigned long long ull;   // packed f32x2 (lo, hi) in an aligned reg pair

__device__ __forceinline__ ull pk2(float a, float b) {
    ull r; asm("mov.b64 %0, {%1, %2};" : "=l"(r) : "f"(a), "f"(b)); return r;
}
__device__ __forceinline__ void upk2(ull v, float& a, float& b) {
    asm("mov.b64 {%0, %1}, %2;" : "=f"(a), "=f"(b) : "l"(v));
}
__device__ __forceinline__ ull fma2(ull a, ull b, ull c) {
    ull d; asm("fma.rn.f32x2 %0, %1, %2, %3;" : "=l"(d) : "l"(a), "l"(b), "l"(c)); return d;
}
__device__ __forceinline__ ull add2(ull a, ull b) {
    ull d; asm("add.rn.f32x2 %0, %1, %2;" : "=l"(d) : "l"(a), "l"(b)); return d;
}

// Batch-invariant constants:
// [0:64)    wfold[p][i]       (folded q/k cross-attn scores)
// [64:72)   bfold[p]
// [72:136)  wv  = ca_w_in rows 16..23   ([j][i])
// [136:200) wo  = ca_w_out              ([e][j])
// [200:208) b_eff[e] = ca_b_out + W_out * bv
__device__ float g_all[208];
__constant__ __align__(16) float c_all[208];

// ---------------------------------------------------------------------------
// Pre-kernel: self-attention over Q (batch invariant) + fold cross-attn q/k.
// ---------------------------------------------------------------------------
__global__ void precompute_kernel(const float* __restrict__ Q,
                                  const float* __restrict__ sa_w_in,
                                  const float* __restrict__ sa_b_in,
                                  const float* __restrict__ sa_w_out,
                                  const float* __restrict__ sa_b_out,
                                  const float* __restrict__ ca_w_in,
                                  const float* __restrict__ ca_b_in,
                                  const float* __restrict__ ca_w_out,
                                  const float* __restrict__ ca_b_out)
{
    if (threadIdx.x != 0) return;

    float qh[4][8], kh[4][8], vh[4][8];
    for (int f = 0; f < 4; f++)
        for (int j = 0; j < 8; j++) {
            float aq = sa_b_in[j], ak = sa_b_in[8 + j], av = sa_b_in[16 + j];
            for (int i = 0; i < 8; i++) {
                float xi = Q[f * 8 + i];
                aq += xi * sa_w_in[j * 8 + i];
                ak += xi * sa_w_in[(8 + j) * 8 + i];
                av += xi * sa_w_in[(16 + j) * 8 + i];
            }
            qh[f][j] = aq; kh[f][j] = ak; vh[f][j] = av;
        }

    float ctx[4][8];
    for (int h = 0; h < 2; h++)
        for (int l = 0; l < 4; l++) {
            float sc[4], mx = -1e30f;
            for (int m = 0; m < 4; m++) {
                float s = 0.f;
                for (int d = 0; d < 4; d++) s += qh[l][h * 4 + d] * kh[m][h * 4 + d];
                sc[m] = s * 0.5f;
                mx = fmaxf(mx, sc[m]);
            }
            float den = 0.f;
            for (int m = 0; m < 4; m++) { sc[m] = expf(sc[m] - mx); den += sc[m]; }
            for (int d = 0; d < 4; d++) {
                float a = 0.f;
                for (int m = 0; m < 4; m++) a += sc[m] * vh[m][h * 4 + d];
                ctx[l][h * 4 + d] = a / den;
            }
        }

    float qupd[4][8];
    for (int f = 0; f < 4; f++)
        for (int e = 0; e < 8; e++) {
            float a = sa_b_out[e];
            for (int j = 0; j < 8; j++) a += ctx[f][j] * sa_w_out[e * 8 + j];
            qupd[f][e] = a;
        }

    float qc[4][8];
    for (int f = 0; f < 4; f++)
        for (int j = 0; j < 8; j++) {
            float a = ca_b_in[j];
            for (int e = 0; e < 8; e++) a += qupd[f][e] * ca_w_in[j * 8 + e];
            qc[f][j] = 0.5f * a;
        }

    for (int h = 0; h < 2; h++)
        for (int f = 0; f < 4; f++) {
            int p = h * 4 + f;
            for (int i = 0; i < 8; i++) {
                float w = 0.f;
                for (int d = 0; d < 4; d++)
                    w += qc[f][h * 4 + d] * ca_w_in[(8 + h * 4 + d) * 8 + i];
                g_all[p * 8 + i] = w;
            }
            float bf = 0.f;
            for (int d = 0; d < 4; d++) bf += qc[f][h * 4 + d] * ca_b_in[8 + h * 4 + d];
            g_all[64 + p] = bf;
        }

    // pack cross-attn v/out weights + effective bias
    for (int k = 0; k < 64; k++) g_all[72 + k]  = ca_w_in[128 + k];   // wv rows 16..23
    for (int k = 0; k < 64; k++) g_all[136 + k] = ca_w_out[k];
    for (int e = 0; e < 8; e++) {
        float be = ca_b_out[e];
        for (int j = 0; j < 8; j++) be += ca_w_out[e * 8 + j] * ca_b_in[16 + j];
        g_all[200 + e] = be;
    }
}

// ---------------------------------------------------------------------------
// Halving-exchange warp reductions. After return, lane holds fully-reduced
// value with index idx = lane >> log2(32/N) (duplicated across 32/N lanes).
// ---------------------------------------------------------------------------
template <int N>
__device__ __forceinline__ void warp_fold_reduce(float* V, int lane) {
    int c = N;
#pragma unroll
    for (int o = 16; o >= 1; o >>= 1) {
        if (c > 1) {
            int half = c >> 1;
#pragma unroll
            for (int j = 0; j < half; j++) {
                float send = (lane & o) ? V[j] : V[j + half];
                float recv = __shfl_xor_sync(FULLMASK, send, o);
                V[j] = ((lane & o) ? V[j + half] : V[j]) + recv;
            }
            c = half;
        } else {
            V[0] += __shfl_xor_sync(FULLMASK, V[0], o);
        }
    }
}

template <int N>
__device__ __forceinline__ void warp_fold_reduce2(ull* V, int lane) {
    int c = N;
#pragma unroll
    for (int o = 16; o >= 1; o >>= 1) {
        if (c > 1) {
            int half = c >> 1;
#pragma unroll
            for (int j = 0; j < half; j++) {
                ull send = (lane & o) ? V[j] : V[j + half];
                ull recv = __shfl_xor_sync(FULLMASK, send, o);
                V[j] = add2((lane & o) ? V[j + half] : V[j], recv);
            }
            c = half;
        } else {
            V[0] = add2(V[0], __shfl_xor_sync(FULLMASK, V[0], o));
        }
    }
}

// ---------------------------------------------------------------------------
// Main kernel: one CTA per batch element. 64 threads, 8 tokens per thread.
// ---------------------------------------------------------------------------
__global__ void __launch_bounds__(64, 9)
afs_main_kernel(const float* __restrict__ x,
                const float* __restrict__ r_w1, const float* __restrict__ r_b1,
                const float* __restrict__ r_w2, const float* __restrict__ r_b2,
                float* __restrict__ out_head, float* __restrict__ out_sim)
{
    const int b = blockIdx.x;
    const int tid = threadIdx.x;
    const int lane = tid & 31;
    const int wid = tid >> 5;

    __shared__ __align__(16) float redA[2][64];   // per-warp A partials
    __shared__ float redS[2][8];                  // per-warp exp-sum partials
    __shared__ __align__(16) float redF[2][32];   // per-warp final-factor partials
    __shared__ float redD[2][4];                  // per-warp sim exp-sum partials
    __shared__ __align__(16) float sQ[32];        // Q_cross [f][e]

    // x tile into registers as packed feature pairs; token t_k = tid + 64*k
    const float4* X4 = reinterpret_cast<const float4*>(x + (size_t)b * 4096);
    ull x2[8][4];
#pragma unroll
    for (int t = 0; t < 8; t++) {
        float4 u0 = __ldcs(&X4[(tid + 64 * t) * 2]);
        float4 u1 = __ldcs(&X4[(tid + 64 * t) * 2 + 1]);
        x2[t][0] = pk2(u0.x, u0.y); x2[t][1] = pk2(u0.z, u0.w);
        x2[t][2] = pk2(u1.x, u1.y); x2[t][3] = pk2(u1.z, u1.w);
    }

    const ull* cw2 = reinterpret_cast<const ull*>(c_all);   // [p*4+h] feature pairs

    // --- phase 1: scores -> exp -> A partials, p chunked in quarters of 2 ---
#pragma unroll
    for (int c = 0; c < 4; c++) {
        ull A2[8];                                 // [pp*4+h]
#pragma unroll
        for (int j = 0; j < 8; j++) A2[j] = 0ull;
        float sums[2] = {0.f, 0.f};

#pragma unroll
        for (int t = 0; t < 8; t++) {
#pragma unroll
            for (int pp = 0; pp < 2; pp++) {
                int p = 2 * c + pp;
                ull acc = fma2(cw2[p * 4 + 0], x2[t][0],
                          fma2(cw2[p * 4 + 1], x2[t][1],
                          fma2(cw2[p * 4 + 2], x2[t][2],
                          fma2(cw2[p * 4 + 3], x2[t][3], 0ull))));
                float slo, shi; upk2(acc, slo, shi);
                float e = __expf(slo + shi + c_all[64 + p]);
                sums[pp] += e;
                ull e2 = pk2(e, e);
#pragma unroll
                for (int h = 0; h < 4; h++)
                    A2[pp * 4 + h] = fma2(e2, x2[t][h], A2[pp * 4 + h]);
            }
        }

        warp_fold_reduce2<8>(A2, lane);            // lane holds packed idx lane>>2
        if (!(lane & 3))
            reinterpret_cast<ull*>(&redA[wid][16 * c])[lane >> 2] = A2[0];

        warp_fold_reduce<2>(sums, lane);           // lane holds idx lane>>4
        if (!(lane & 15)) redS[wid][2 * c + (lane >> 4)] = sums[0];
    }

    __syncthreads();

    // --- warp 0: ctx + Q_cross (constant-bank weights, no L1 traffic) ---
    if (wid == 0) {
        int f = lane >> 3, j = lane & 7;       // lane <-> (f, j)
        int h = j >> 2, p = h * 4 + f;
        float At[8];
#pragma unroll
        for (int i = 0; i < 8; i++) At[i] = 0.f;
        float den = 0.f;
#pragma unroll
        for (int w = 0; w < 2; w++) {
            const float4* r4 = reinterpret_cast<const float4*>(&redA[w][p * 8]);
            float4 v0 = r4[0], v1 = r4[1];
            At[0] += v0.x; At[1] += v0.y; At[2] += v0.z; At[3] += v0.w;
            At[4] += v1.x; At[5] += v1.y; At[6] += v1.z; At[7] += v1.w;
            den += redS[w][p];
        }

        float accv = 0.f;
#pragma unroll
        for (int i = 0; i < 8; i++) accv = fmaf(c_all[72 + j * 8 + i], At[i], accv);
        float ctxv = accv / den;                 // bias folded into b_eff

        float q = c_all[200 + j];                // b_eff[e=j]
#pragma unroll
        for (int jj = 0; jj < 8; jj++) {
            float cv = __shfl_sync(FULLMASK, ctxv, f * 8 + jj);
            q = fmaf(c_all[136 + j * 8 + jj], cv, q);
        }
        sQ[f * 8 + j] = q;
    }
    __syncthreads();

    // --- phase 2: similarity (raw out), exp, FF + denom; f chunked in halves ---
    const ull* sQ2 = reinterpret_cast<const ull*>(sQ);   // [f*4+h]
    float* simbase = out_sim + (size_t)b * 2048;
#pragma unroll
    for (int c = 0; c < 2; c++) {
        ull FF2[8];                                      // [ff*4+h]
#pragma unroll
        for (int j = 0; j < 8; j++) FF2[j] = 0ull;
        float ds[2] = {0.f, 0.f};

#pragma unroll
        for (int t = 0; t < 8; t++) {
#pragma unroll
            for (int ff = 0; ff < 2; ff++) {
                int f = 2 * c + ff;
                ull acc = fma2(sQ2[f * 4 + 0], x2[t][0],
                          fma2(sQ2[f * 4 + 1], x2[t][1],
                          fma2(sQ2[f * 4 + 2], x2[t][2],
                          fma2(sQ2[f * 4 + 3], x2[t][3], 0ull))));
                float slo, shi; upk2(acc, slo, shi);
                float s = slo + shi;
                __stcs(&simbase[f * 512 + tid + 64 * t], s);   // pre-softmax sim
                float e = __expf(s);
                ds[ff] += e;
                ull e2 = pk2(e, e);
#pragma unroll
                for (int h = 0; h < 4; h++)
                    FF2[ff * 4 + h] = fma2(e2, x2[t][h], FF2[ff * 4 + h]);
            }
        }

        warp_fold_reduce2<8>(FF2, lane);
        if (!(lane & 3))
            reinterpret_cast<ull*>(&redF[wid][16 * c])[lane >> 2] = FF2[0];

        warp_fold_reduce<2>(ds, lane);
        if (!(lane & 15)) redD[wid][2 * c + (lane >> 4)] = ds[0];
    }

    __syncthreads();

    // --- warp 0: normalize final factors + regression head (coalesced) ---
    if (wid == 0) {
        float s = 0.f;
#pragma unroll
        for (int w = 0; w < 2; w++) s += redF[w][lane];
        int f = lane >> 3;
        float den = 0.f;
#pragma unroll
        for (int w = 0; w < 2; w++) den += redD[w][f];
        float fused = s / den;          // lane k holds fused[k], k = f*8+e

        // hp[h] = r_w1[h][lane] * fused[lane]; coalesced loads, then fold<16>
        float hp[16];
#pragma unroll
        for (int h = 0; h < 16; h++)
            hp[h] = r_w1[h * 32 + lane] * fused;
        warp_fold_reduce<16>(hp, lane);          // lane holds h = lane>>1

        int h = lane >> 1;
        float hv = fmaxf(hp[0] + r_b1[h], 0.f);
        float o = (lane & 1) ? 0.f : hv * r_w2[h];
#pragma unroll
        for (int off = 16; off >= 1; off >>= 1)
            o += __shfl_xor_sync(FULLMASK, o, off);
        if (lane == 0) out_head[b] = o + r_b2[0];
    }
}

// ---------------------------------------------------------------------------
extern "C" void kernel_launch(void* const* d_in, const int* in_sizes, int n_in,
                              void* d_out, int out_size)
{
    const float* x        = (const float*)d_in[0];
    const float* Q        = (const float*)d_in[1];
    const float* sa_w_in  = (const float*)d_in[2];
    const float* sa_b_in  = (const float*)d_in[3];
    const float* sa_w_out = (const float*)d_in[4];
    const float* sa_b_out = (const float*)d_in[5];
    const float* ca_w_in  = (const float*)d_in[6];
    const float* ca_b_in  = (const float*)d_in[7];
    const float* ca_w_out = (const float*)d_in[8];
    const float* ca_b_out = (const float*)d_in[9];
    const float* r_w1     = (const float*)d_in[10];
    const float* r_b1     = (const float*)d_in[11];
    const float* r_w2     = (const float*)d_in[12];
    const float* r_b2     = (const float*)d_in[13];

    int B = in_sizes[0] / (512 * 8);

    float* out = (float*)d_out;
    float* out_head = out;       // (out, similarity) tuple order: out first
    float* out_sim  = out + B;   // then [B, 4, 512] similarity

    precompute_kernel<<<1, 32>>>(Q, sa_w_in, sa_b_in, sa_w_out, sa_b_out,
                                 ca_w_in, ca_b_in, ca_w_out, ca_b_out);

    // copy all folded/packed batch-invariant weights into the constant bank
    void* pAll = nullptr;
    cudaGetSymbolAddress(&pAll, g_all);
    cudaMemcpyToSymbolAsync(c_all, pAll, 208 * sizeof(float), 0,
                            cudaMemcpyDeviceToDevice, 0);

    afs_main_kernel<<<B, 64>>>(x, r_w1, r_b1, r_w2, r_b2, out_head, out_sim);
}